// round 4
// baseline (speedup 1.0000x reference)
#include <cuda_runtime.h>
#include <math.h>

// ---------------- static config ----------------
#define Hh   376
#define Ww   376
#define HW   (376*376)          // 141376
#define CIN  256
#define CSH  64
#define NB   6
#define KTOP 500
#define NSCORE (3*HW)           // 424128
#define BN_EPS 1e-5f

// ---------------- scratch (device globals; no runtime alloc) ----------------
__device__ float g_shared[CSH*HW];        // shared conv output (post BN+ReLU)
__device__ float g_h[NB*CSH*HW];          // branch hidden activations
__device__ float g_score[3*HW];           // sigmoid(hm)
__device__ float g_reg[9*HW];             // center(2), cz(1), dim(3), rot(2), iou(1)

__device__ unsigned int g_hist[2048];
__device__ unsigned int g_prefix;
__device__ unsigned int g_kRem;
__device__ unsigned int g_cntA;
__device__ unsigned int g_cntB;
__device__ unsigned int g_thresh;
__device__ unsigned int g_needEq;
__device__ unsigned long long g_listA[512];
__device__ unsigned int g_listB[4096];

// slot map: branch -> global reg slot per out-channel (-1 = unused)
__device__ __constant__ int c_slot[NB][3] = {
    {-1,-1,-1},   // hm handled separately (g_score)
    { 0, 1,-1},   // center
    { 2,-1,-1},   // center_z
    { 3, 4, 5},   // dim
    { 6, 7,-1},   // rot
    { 8,-1,-1}    // iou
};

// ================= shared conv: 256 -> 64, 3x3, BN + ReLU =================
// block: 256 threads, tile = 1 row x 64 px, thread computes 4 oc x 4 px
#define TW 64
__global__ void conv_shared_kernel(const float* __restrict__ x,
                                   const float* __restrict__ Wsh,
                                   const float* __restrict__ bns)
{
    __shared__ float s_in[3][TW+2];
    __shared__ float s_w[CSH*9];

    const int y  = blockIdx.y;
    const int x0 = blockIdx.x * TW;
    const int t  = threadIdx.x;
    const int pg = t & 15;       // pixel group (16 groups x 4 px)
    const int og = t >> 4;       // oc group    (16 groups x 4 oc)

    float acc[4][4];
    #pragma unroll
    for (int o = 0; o < 4; o++)
        #pragma unroll
        for (int p = 0; p < 4; p++) acc[o][p] = 0.f;

    for (int c = 0; c < CIN; c++) {
        // input halo tile: 3 rows x (TW+2)
        for (int i = t; i < 3*(TW+2); i += 256) {
            int ry = i / (TW+2), rx = i % (TW+2);
            int gy = y + ry - 1, gx = x0 + rx - 1;
            float v = 0.f;
            if (gy >= 0 && gy < Hh && gx >= 0 && gx < Ww)
                v = x[c*HW + gy*Ww + gx];
            s_in[ry][rx] = v;
        }
        // weights for this input channel: 64 oc x 9
        for (int i = t; i < CSH*9; i += 256) {
            int oc = i / 9, k = i % 9;
            s_w[i] = Wsh[(oc*CIN + c)*9 + k];
        }
        __syncthreads();

        const int px0 = pg*4;
        #pragma unroll
        for (int ky = 0; ky < 3; ky++) {
            float vin[6];
            #pragma unroll
            for (int j = 0; j < 6; j++) vin[j] = s_in[ky][px0 + j];
            #pragma unroll
            for (int o = 0; o < 4; o++) {
                const int oc = og*4 + o;
                float w0 = s_w[oc*9 + ky*3 + 0];
                float w1 = s_w[oc*9 + ky*3 + 1];
                float w2 = s_w[oc*9 + ky*3 + 2];
                #pragma unroll
                for (int p = 0; p < 4; p++)
                    acc[o][p] += w0*vin[p] + w1*vin[p+1] + w2*vin[p+2];
            }
        }
        __syncthreads();
    }

    #pragma unroll
    for (int o = 0; o < 4; o++) {
        const int oc = og*4 + o;
        float g = bns[0*CSH+oc], b = bns[1*CSH+oc];
        float m = bns[2*CSH+oc], v = bns[3*CSH+oc];
        float sc = g * rsqrtf(v + BN_EPS);
        float sh = b - m*sc;
        #pragma unroll
        for (int p = 0; p < 4; p++) {
            int gx = x0 + pg*4 + p;
            if (gx < Ww)
                g_shared[oc*HW + y*Ww + gx] = fmaxf(acc[o][p]*sc + sh, 0.f);
        }
    }
}

// ================= branch conv1: 64 -> 64, 3x3, BN + ReLU (x6) =================
__global__ void conv1_kernel(const float* __restrict__ W1s,
                             const float* __restrict__ bn1s)
{
    __shared__ float s_in[3][TW+2];
    __shared__ float s_w[CSH*9];

    const int br = blockIdx.z;
    const float* __restrict__ Win = W1s + (size_t)br*CSH*CSH*9;
    const float* __restrict__ bns = bn1s + br*4*CSH;
    float* __restrict__ outp = g_h + (size_t)br*CSH*HW;

    const int y  = blockIdx.y;
    const int x0 = blockIdx.x * TW;
    const int t  = threadIdx.x;
    const int pg = t & 15;
    const int og = t >> 4;

    float acc[4][4];
    #pragma unroll
    for (int o = 0; o < 4; o++)
        #pragma unroll
        for (int p = 0; p < 4; p++) acc[o][p] = 0.f;

    for (int c = 0; c < CSH; c++) {
        for (int i = t; i < 3*(TW+2); i += 256) {
            int ry = i / (TW+2), rx = i % (TW+2);
            int gy = y + ry - 1, gx = x0 + rx - 1;
            float v = 0.f;
            if (gy >= 0 && gy < Hh && gx >= 0 && gx < Ww)
                v = g_shared[c*HW + gy*Ww + gx];
            s_in[ry][rx] = v;
        }
        for (int i = t; i < CSH*9; i += 256) {
            int oc = i / 9, k = i % 9;
            s_w[i] = Win[(oc*CSH + c)*9 + k];
        }
        __syncthreads();

        const int px0 = pg*4;
        #pragma unroll
        for (int ky = 0; ky < 3; ky++) {
            float vin[6];
            #pragma unroll
            for (int j = 0; j < 6; j++) vin[j] = s_in[ky][px0 + j];
            #pragma unroll
            for (int o = 0; o < 4; o++) {
                const int oc = og*4 + o;
                float w0 = s_w[oc*9 + ky*3 + 0];
                float w1 = s_w[oc*9 + ky*3 + 1];
                float w2 = s_w[oc*9 + ky*3 + 2];
                #pragma unroll
                for (int p = 0; p < 4; p++)
                    acc[o][p] += w0*vin[p] + w1*vin[p+1] + w2*vin[p+2];
            }
        }
        __syncthreads();
    }

    #pragma unroll
    for (int o = 0; o < 4; o++) {
        const int oc = og*4 + o;
        float g = bns[0*CSH+oc], b = bns[1*CSH+oc];
        float m = bns[2*CSH+oc], v = bns[3*CSH+oc];
        float sc = g * rsqrtf(v + BN_EPS);
        float sh = b - m*sc;
        #pragma unroll
        for (int p = 0; p < 4; p++) {
            int gx = x0 + pg*4 + p;
            if (gx < Ww)
                outp[oc*HW + y*Ww + gx] = fmaxf(acc[o][p]*sc + sh, 0.f);
        }
    }
}

// ================= branch conv2: 64 -> 3, 3x3 + bias (x6) =================
// block: 384 threads, tile = 1 row x 128 px, thread = 1 oc x 1 px
#define TW2 128
__global__ void conv2_kernel(const float* __restrict__ W2s,
                             const float* __restrict__ b2s)
{
    __shared__ float s_in[3][TW2+2];
    __shared__ float s_w[3*9];

    const int br = blockIdx.z;
    const float* __restrict__ in = g_h + (size_t)br*CSH*HW;
    const float* __restrict__ Wb = W2s + (size_t)br*3*CSH*9;

    const int y  = blockIdx.y;
    const int x0 = blockIdx.x * TW2;
    const int t  = threadIdx.x;
    const int px = t % TW2;
    const int oc = t / TW2;      // 0..2

    float acc = 0.f;
    for (int c = 0; c < CSH; c++) {
        for (int i = t; i < 3*(TW2+2); i += 384) {
            int ry = i / (TW2+2), rx = i % (TW2+2);
            int gy = y + ry - 1, gx = x0 + rx - 1;
            float v = 0.f;
            if (gy >= 0 && gy < Hh && gx >= 0 && gx < Ww)
                v = in[c*HW + gy*Ww + gx];
            s_in[ry][rx] = v;
        }
        if (t < 27)
            s_w[t] = Wb[((t/9)*CSH + c)*9 + (t%9)];
        __syncthreads();

        #pragma unroll
        for (int ky = 0; ky < 3; ky++)
            #pragma unroll
            for (int kx = 0; kx < 3; kx++)
                acc += s_w[oc*9 + ky*3 + kx] * s_in[ky][px + kx];
        __syncthreads();
    }

    int gx = x0 + px;
    if (gx < Ww) {
        acc += b2s[br*3 + oc];
        int p = y*Ww + gx;
        if (br == 0) {
            g_score[oc*HW + p] = 1.f / (1.f + expf(-acc));
        } else {
            int slot = c_slot[br][oc];
            if (slot >= 0) g_reg[slot*HW + p] = acc;
        }
    }
}

// ================= exact top-K: 3-pass radix select =================
__global__ void init_kernel() {
    g_prefix = 0u; g_kRem = KTOP; g_cntA = 0u; g_cntB = 0u;
}

__global__ void zero_hist_kernel() {
    int i = blockIdx.x * blockDim.x + threadIdx.x;
    if (i < 2048) g_hist[i] = 0u;
}

__global__ void hist_kernel(unsigned int prefMask, int shift, int bits) {
    __shared__ unsigned int sh[2048];
    const int nb = 1 << bits;
    for (int i = threadIdx.x; i < nb; i += blockDim.x) sh[i] = 0u;
    __syncthreads();
    const unsigned int pref = g_prefix;
    for (int i = blockIdx.x*blockDim.x + threadIdx.x; i < NSCORE;
         i += gridDim.x*blockDim.x) {
        unsigned int key = __float_as_uint(g_score[i]);
        if ((key & prefMask) == pref)
            atomicAdd(&sh[(key >> shift) & (nb-1)], 1u);
    }
    __syncthreads();
    for (int i = threadIdx.x; i < nb; i += blockDim.x)
        if (sh[i]) atomicAdd(&g_hist[i], sh[i]);
}

__global__ void scan_kernel(int shift, int bits, int last) {
    unsigned int kRem = g_kRem;
    const int nb = 1 << bits;
    for (int b = nb - 1; b >= 0; b--) {
        unsigned int c = g_hist[b];
        if (c >= kRem) { g_prefix |= ((unsigned int)b << shift); break; }
        kRem -= c;
    }
    g_kRem = kRem;
    if (last) { g_thresh = g_prefix; g_needEq = kRem; }
}

__global__ void compact_kernel() {
    const unsigned int T = g_thresh;
    for (int i = blockIdx.x*blockDim.x + threadIdx.x; i < NSCORE;
         i += gridDim.x*blockDim.x) {
        unsigned int key = __float_as_uint(g_score[i]);
        if (key > T) {
            unsigned int p = atomicAdd(&g_cntA, 1u);
            if (p < 512u)
                g_listA[p] = ((unsigned long long)key << 32) |
                             (unsigned int)(~(unsigned int)i);
        } else if (key == T) {
            unsigned int p = atomicAdd(&g_cntB, 1u);
            if (p < 4096u) g_listB[p] = (unsigned int)i;
        }
    }
}

// ================= final sort + decode =================
__global__ void final_kernel(float* __restrict__ out) {
    __shared__ unsigned long long comp[512];
    __shared__ unsigned int tie[4096];

    const int t = threadIdx.x;   // 512
    const unsigned int cntA = min(g_cntA, 512u);
    const unsigned int need = g_needEq;
    const unsigned int cntB = min(g_cntB, 4096u);
    const unsigned int T = g_thresh;

    // sort tie indices ascending (jax tie-break: lowest index first)
    for (int i = t; i < 4096; i += 512)
        tie[i] = (i < (int)cntB) ? g_listB[i] : 0xFFFFFFFFu;
    __syncthreads();
    for (int k = 2; k <= 4096; k <<= 1) {
        for (int j = k >> 1; j > 0; j >>= 1) {
            for (int i = t; i < 4096; i += 512) {
                int ixj = i ^ j;
                if (ixj > i) {
                    unsigned int a = tie[i], b = tie[ixj];
                    if ((i & k) == 0) { if (a > b) { tie[i] = b; tie[ixj] = a; } }
                    else             { if (a < b) { tie[i] = b; tie[ixj] = a; } }
                }
            }
            __syncthreads();
        }
    }

    // build composite list: strictly-greater + needed ties
    unsigned long long myc = 0ull;
    if (t < (int)cntA) {
        myc = g_listA[t];
    } else if (t < (int)(cntA + need)) {
        unsigned int r = t - cntA;
        if (r < cntB)
            myc = ((unsigned long long)T << 32) | (unsigned int)(~tie[r]);
    }
    comp[t] = myc;
    __syncthreads();

    // ascending bitonic sort on (key<<32)|~idx  (largest = best rank)
    for (int k = 2; k <= 512; k <<= 1) {
        for (int j = k >> 1; j > 0; j >>= 1) {
            int ixj = t ^ j;
            if (ixj > t) {
                unsigned long long a = comp[t], b = comp[ixj];
                if ((t & k) == 0) { if (a > b) { comp[t] = b; comp[ixj] = a; } }
                else              { if (a < b) { comp[t] = b; comp[ixj] = a; } }
            }
            __syncthreads();
        }
    }

    if (t < KTOP) {
        unsigned long long c = comp[511 - t];      // rank t (descending)
        unsigned int key = (unsigned int)(c >> 32);
        unsigned int idx = ~((unsigned int)(c & 0xFFFFFFFFull));
        float score = __uint_as_float(key);
        int cls = (int)(idx / HW);
        int sp  = (int)(idx % HW);
        float xs = (float)(sp % Ww);
        float ys = (float)(sp / Ww);

        float cx = g_reg[0*HW + sp], cy = g_reg[1*HW + sp];
        float cz = g_reg[2*HW + sp];
        float d0 = expf(g_reg[3*HW + sp]);
        float d1 = expf(g_reg[4*HW + sp]);
        float d2 = expf(g_reg[5*HW + sp]);
        float rc = g_reg[6*HW + sp], rs = g_reg[7*HW + sp];
        float iou = g_reg[8*HW + sp];

        float xg = ((xs + cx) * 4.0f) * 0.1f + (-75.2f);
        float yg = ((ys + cy) * 4.0f) * 0.1f + (-75.2f);
        float heading = atan2f(rs, rc);

        iou = fminf(fmaxf((iou + 1.0f) * 0.5f, 0.0f), 1.0f);
        const float RECT[3] = {0.68f, 0.71f, 0.65f};
        float r = RECT[cls];
        float sc = powf(score, 1.0f - r) * powf(iou, r);
        sc = (sc > 0.1f) ? sc : 0.0f;

        out[t*7 + 0] = xg;
        out[t*7 + 1] = yg;
        out[t*7 + 2] = cz;
        out[t*7 + 3] = d0;
        out[t*7 + 4] = d1;
        out[t*7 + 5] = d2;
        out[t*7 + 6] = heading;
        out[KTOP*7 + t]        = sc;
        out[KTOP*7 + KTOP + t] = (float)cls;
    }
}

// ================= launch =================
extern "C" void kernel_launch(void* const* d_in, const int* in_sizes, int n_in,
                              void* d_out, int out_size)
{
    const float* x    = (const float*)d_in[0];
    const float* Wsh  = (const float*)d_in[1];
    const float* bnsh = (const float*)d_in[2];
    const float* W1s  = (const float*)d_in[3];
    const float* bn1s = (const float*)d_in[4];
    const float* W2s  = (const float*)d_in[5];
    const float* b2s  = (const float*)d_in[6];
    float* out = (float*)d_out;

    conv_shared_kernel<<<dim3((Ww+TW-1)/TW, Hh), 256>>>(x, Wsh, bnsh);
    conv1_kernel<<<dim3((Ww+TW-1)/TW, Hh, NB), 256>>>(W1s, bn1s);
    conv2_kernel<<<dim3((Ww+TW2-1)/TW2, Hh, NB), 384>>>(W2s, b2s);

    init_kernel<<<1,1>>>();
    // pass 0: bits [31:21]
    zero_hist_kernel<<<2,1024>>>();
    hist_kernel<<<512,256>>>(0x00000000u, 21, 11);
    scan_kernel<<<1,1>>>(21, 11, 0);
    // pass 1: bits [20:10]
    zero_hist_kernel<<<2,1024>>>();
    hist_kernel<<<512,256>>>(0xFFE00000u, 10, 11);
    scan_kernel<<<1,1>>>(10, 11, 0);
    // pass 2: bits [9:0]
    zero_hist_kernel<<<2,1024>>>();
    hist_kernel<<<512,256>>>(0xFFFFFC00u, 0, 10);
    scan_kernel<<<1,1>>>(0, 10, 1);

    compact_kernel<<<512,256>>>();
    final_kernel<<<1,512>>>(out);
}

// round 7
// speedup vs baseline: 1.3940x; 1.3940x over previous
#include <cuda_runtime.h>
#include <math.h>

// ---------------- static config ----------------
#define Hh   376
#define Ww   376
#define HW   (376*376)          // 141376
#define CIN  256
#define CSH  64
#define NB   6
#define KTOP 500
#define NSCORE (3*HW)           // 424128
#define BN_EPS 1e-5f

// ---------------- scratch (device globals; no runtime alloc) ----------------
__device__ float g_shared[CSH*HW];        // shared conv output (post BN+ReLU)
__device__ float g_h[NB*CSH*HW];          // branch hidden activations
__device__ float g_score[3*HW];           // sigmoid(hm)
__device__ float g_reg[9*HW];             // center(2), cz(1), dim(3), rot(2), iou(1)

// Winograd transformed weights (BN scale folded) + bias
__device__ float g_U_sh[16*CIN*CSH];      // [k][ci][co]
__device__ float g_U_br[NB*16*CSH*CSH];   // [br][k][ci][co]
__device__ float g_bias_sh[CSH];
__device__ float g_bias_br[NB*CSH];

__device__ unsigned int g_hist[2048];
__device__ unsigned int g_prefix;
__device__ unsigned int g_kRem;
__device__ unsigned int g_cntA;
__device__ unsigned int g_cntB;
__device__ unsigned int g_thresh;
__device__ unsigned int g_needEq;
__device__ unsigned long long g_listA[512];
__device__ unsigned int g_listB[4096];

// slot map: branch -> global reg slot per out-channel (-1 = unused)
__device__ __constant__ int c_slot[NB][3] = {
    {-1,-1,-1},   // hm handled separately (g_score)
    { 0, 1,-1},   // center
    { 2,-1,-1},   // center_z
    { 3, 4, 5},   // dim
    { 6, 7,-1},   // rot
    { 8,-1,-1}    // iou
};

// ================= weight transform: U = (G g G^T) * bn_scale ==============
// mode 0: shared conv (cin=256), mode 1: branches (grid.y = branch, cin=64)
__global__ void wtrans_kernel(const float* __restrict__ W,
                              const float* __restrict__ bn,
                              int cin, int mode)
{
    float* U;
    float* bias;
    if (mode == 0) {
        U = g_U_sh; bias = g_bias_sh;
    } else {
        int br = blockIdx.y;
        W  += (size_t)br * CSH * CSH * 9;
        bn += br * 4 * CSH;
        U = g_U_br + (size_t)br * 16 * CSH * CSH;
        bias = g_bias_br + br * CSH;
    }
    int idx = blockIdx.x * blockDim.x + threadIdx.x;
    if (idx >= 64 * cin) return;
    int co = idx / cin, ci = idx % cin;

    float scale = bn[0*CSH+co] * rsqrtf(bn[3*CSH+co] + BN_EPS);
    float g[9];
    #pragma unroll
    for (int k = 0; k < 9; k++) g[k] = W[(size_t)(co*cin + ci)*9 + k] * scale;

    // t = G g  (4x3)
    float t[4][3];
    #pragma unroll
    for (int c = 0; c < 3; c++) {
        t[0][c] = g[0*3+c];
        t[1][c] = 0.5f*(g[0*3+c] + g[1*3+c] + g[2*3+c]);
        t[2][c] = 0.5f*(g[0*3+c] - g[1*3+c] + g[2*3+c]);
        t[3][c] = g[2*3+c];
    }
    // u = t G^T (4x4)
    #pragma unroll
    for (int r = 0; r < 4; r++) {
        float u0 = t[r][0];
        float u1 = 0.5f*(t[r][0] + t[r][1] + t[r][2]);
        float u2 = 0.5f*(t[r][0] - t[r][1] + t[r][2]);
        float u3 = t[r][2];
        U[(size_t)(r*4+0)*cin*64 + ci*64 + co] = u0;
        U[(size_t)(r*4+1)*cin*64 + ci*64 + co] = u1;
        U[(size_t)(r*4+2)*cin*64 + ci*64 + co] = u2;
        U[(size_t)(r*4+3)*cin*64 + ci*64 + co] = u3;
    }
    if (ci == 0) bias[co] = bn[1*CSH+co] - bn[2*CSH+co]*scale;
}

// ================= fused Winograd F(2x2,3x3) conv + BN + ReLU ==============
// block: 512 threads = 16 warps; warp k owns transform point k.
// tile block: 32 tiles horizontally (64 out px) x 1 tile row (2 out rows).
// thread GEMM tile: 8 cout x 8 tiles, accumulate over cin in chunks of 8.
// mode 0: x -> g_shared (cin=256); mode 1: g_shared -> g_h[branch] (cin=64)
#define S_IN 0                  // 8 * 4 * 68 = 2176 floats
#define S_U  2176               // 8 * 16 * 64 = 8192
#define S_V  10368              // 8 * 16 * 32 = 4096
// s_M overlaps everything: 16*64*32 = 32768 floats = 128KB

__global__ void __launch_bounds__(512, 1)
winograd_kernel(const float* __restrict__ xin, int mode, int cin)
{
    extern __shared__ float sm[];

    const float* in;
    const float* U;
    const float* bias;
    float* out;
    if (mode == 0) {
        in = xin; U = g_U_sh; bias = g_bias_sh; out = g_shared;
    } else {
        int br = blockIdx.z;
        in = g_shared;
        U = g_U_br + (size_t)br * 16 * CSH * CSH;
        bias = g_bias_br + br * CSH;
        out = g_h + (size_t)br * CSH * HW;
    }

    const int tid = threadIdx.x;
    const int k = tid >> 5;            // transform point (warp)
    const int lane = tid & 31;
    const int co0 = (lane >> 2) * 8;
    const int t0 = (lane & 3) * 8;

    const int T0 = blockIdx.x * 32;    // first tile index (x)
    const int x0px = T0*2 - 1;         // leftmost input col
    const int y0px = (int)blockIdx.y*2 - 1;

    float acc[8][8];
    #pragma unroll
    for (int a = 0; a < 8; a++)
        #pragma unroll
        for (int b = 0; b < 8; b++) acc[a][b] = 0.f;

    for (int chunk = 0; chunk < cin; chunk += 8) {
        __syncthreads();
        // ---- stage raw input: 8 ci x 4 rows x 66 cols ----
        for (int i = tid; i < 8*264; i += 512) {
            int ci = i / 264; int rem = i - ci*264;
            int r = rem / 66, c = rem - r*66;
            int iy = y0px + r, ix = x0px + c;
            float v = 0.f;
            if ((unsigned)iy < (unsigned)Hh && (unsigned)ix < (unsigned)Ww)
                v = in[(size_t)(chunk+ci)*HW + iy*Ww + ix];
            sm[S_IN + ci*272 + r*68 + c] = v;
        }
        // ---- stage U: 16k x 8ci x 64co (float4) ----
        {
            const float4* Ug = (const float4*)U;
            for (int f = tid; f < 2048; f += 512) {
                int kk = f >> 7;
                int ci = (f >> 4) & 7;
                int c4 = f & 15;
                float4 val = Ug[(size_t)kk*cin*16 + (chunk+ci)*16 + c4];
                *(float4*)&sm[S_U + ci*1024 + kk*64 + c4*4] = val;
            }
        }
        __syncthreads();
        // ---- input transform: V = B^T d B, 8ci x 32 tiles ----
        if (tid < 256) {
            int ci = tid >> 5, t = tid & 31;
            const float* dbase = &sm[S_IN + ci*272];
            float d[4][4];
            #pragma unroll
            for (int r = 0; r < 4; r++)
                #pragma unroll
                for (int c = 0; c < 4; c++)
                    d[r][c] = dbase[r*68 + 2*t + c];
            float z[4][4];
            #pragma unroll
            for (int c = 0; c < 4; c++) {
                z[0][c] = d[0][c] - d[2][c];
                z[1][c] = d[1][c] + d[2][c];
                z[2][c] = d[2][c] - d[1][c];
                z[3][c] = d[1][c] - d[3][c];
            }
            float* vb = &sm[S_V + ci*512];
            #pragma unroll
            for (int r = 0; r < 4; r++) {
                vb[(r*4+0)*32 + t] = z[r][0] - z[r][2];
                vb[(r*4+1)*32 + t] = z[r][1] + z[r][2];
                vb[(r*4+2)*32 + t] = z[r][2] - z[r][1];
                vb[(r*4+3)*32 + t] = z[r][1] - z[r][3];
            }
        }
        __syncthreads();
        // ---- GEMM: acc[co][t] += U_k[co] * V_k[t] over 8 cin ----
        #pragma unroll
        for (int ci = 0; ci < 8; ci++) {
            float4 ua = *(const float4*)&sm[S_U + ci*1024 + k*64 + co0];
            float4 ub = *(const float4*)&sm[S_U + ci*1024 + k*64 + co0 + 4];
            float4 va = *(const float4*)&sm[S_V + ci*512  + k*32 + t0];
            float4 vb = *(const float4*)&sm[S_V + ci*512  + k*32 + t0 + 4];
            float u[8] = {ua.x,ua.y,ua.z,ua.w, ub.x,ub.y,ub.z,ub.w};
            float v[8] = {va.x,va.y,va.z,va.w, vb.x,vb.y,vb.z,vb.w};
            #pragma unroll
            for (int a = 0; a < 8; a++)
                #pragma unroll
                for (int b = 0; b < 8; b++)
                    acc[a][b] = fmaf(u[a], v[b], acc[a][b]);
        }
    }

    // ---- cross-warp output transform via smem M buffer ----
    __syncthreads();
    #pragma unroll
    for (int a = 0; a < 8; a++) {
        float4 lo = make_float4(acc[a][0], acc[a][1], acc[a][2], acc[a][3]);
        float4 hi = make_float4(acc[a][4], acc[a][5], acc[a][6], acc[a][7]);
        *(float4*)&sm[k*2048 + (co0+a)*32 + t0]     = lo;
        *(float4*)&sm[k*2048 + (co0+a)*32 + t0 + 4] = hi;
    }
    __syncthreads();

    const int gy = blockIdx.y * 2;
    for (int task = tid; task < 2048; task += 512) {
        int co = task >> 5, t = task & 31;
        float m[16];
        #pragma unroll
        for (int kk = 0; kk < 16; kk++) m[kk] = sm[kk*2048 + co*32 + t];
        float p0[4], p1[4];
        #pragma unroll
        for (int c = 0; c < 4; c++) {
            p0[c] = m[c] + m[4+c] + m[8+c];
            p1[c] = m[4+c] - m[8+c] - m[12+c];
        }
        float bi = bias[co];
        float y00 = fmaxf(p0[0]+p0[1]+p0[2] + bi, 0.f);
        float y01 = fmaxf(p0[1]-p0[2]-p0[3] + bi, 0.f);
        float y10 = fmaxf(p1[0]+p1[1]+p1[2] + bi, 0.f);
        float y11 = fmaxf(p1[1]-p1[2]-p1[3] + bi, 0.f);
        int gx = (T0 + t) * 2;
        if (gx < Ww) {
            float* o = out + (size_t)co*HW + gy*Ww + gx;
            *(float2*)o         = make_float2(y00, y01);
            *(float2*)(o + Ww)  = make_float2(y10, y11);
        }
    }
}

// ================= branch conv2: 64 -> 3, 3x3 + bias (x6) =================
// block: 128 threads, tile = 4 rows x 128 px, thread = 1 px x 3 oc x 4 rows
#define C2W 128
__global__ void conv2_kernel(const float* __restrict__ W2s,
                             const float* __restrict__ b2s)
{
    __shared__ float s_in[6][C2W+2];
    __shared__ float s_w[27];

    const int br = blockIdx.z;
    const float* __restrict__ in = g_h + (size_t)br*CSH*HW;
    const float* __restrict__ Wb = W2s + (size_t)br*3*CSH*9;

    const int y0 = blockIdx.y * 4;
    const int x0 = blockIdx.x * C2W;
    const int t  = threadIdx.x;

    float acc[4][3];
    #pragma unroll
    for (int j = 0; j < 4; j++)
        #pragma unroll
        for (int o = 0; o < 3; o++) acc[j][o] = 0.f;

    for (int c = 0; c < CSH; c++) {
        __syncthreads();
        for (int i = t; i < 6*(C2W+2); i += C2W) {
            int r = i / (C2W+2), cc = i % (C2W+2);
            int iy = y0 - 1 + r, ix = x0 - 1 + cc;
            float v = 0.f;
            if ((unsigned)iy < (unsigned)Hh && (unsigned)ix < (unsigned)Ww)
                v = in[c*HW + iy*Ww + ix];
            s_in[r][cc] = v;
        }
        if (t < 27) s_w[t] = Wb[((t/9)*CSH + c)*9 + (t%9)];
        __syncthreads();

        float w[3][9];
        #pragma unroll
        for (int o = 0; o < 3; o++)
            #pragma unroll
            for (int kk = 0; kk < 9; kk++) w[o][kk] = s_w[o*9+kk];

        #pragma unroll
        for (int r = 0; r < 6; r++) {
            float a0 = s_in[r][t], a1 = s_in[r][t+1], a2 = s_in[r][t+2];
            #pragma unroll
            for (int j = 0; j < 4; j++) {
                int ky = r - j;
                if (ky >= 0 && ky < 3) {
                    #pragma unroll
                    for (int o = 0; o < 3; o++)
                        acc[j][o] += w[o][ky*3]*a0 + w[o][ky*3+1]*a1 + w[o][ky*3+2]*a2;
                }
            }
        }
    }

    int gx = x0 + t;
    if (gx < Ww) {
        #pragma unroll
        for (int j = 0; j < 4; j++) {
            int p = (y0+j)*Ww + gx;
            #pragma unroll
            for (int o = 0; o < 3; o++) {
                float v = acc[j][o] + b2s[br*3 + o];
                if (br == 0) {
                    g_score[o*HW + p] = 1.f / (1.f + expf(-v));
                } else {
                    int slot = c_slot[br][o];
                    if (slot >= 0) g_reg[slot*HW + p] = v;
                }
            }
        }
    }
}

// ================= exact top-K: 3-pass radix select =================
__global__ void init_kernel() {
    g_prefix = 0u; g_kRem = KTOP; g_cntA = 0u; g_cntB = 0u;
}

__global__ void zero_hist_kernel() {
    int i = blockIdx.x * blockDim.x + threadIdx.x;
    if (i < 2048) g_hist[i] = 0u;
}

__global__ void hist_kernel(unsigned int prefMask, int shift, int bits) {
    __shared__ unsigned int sh[2048];
    const int nb = 1 << bits;
    for (int i = threadIdx.x; i < nb; i += blockDim.x) sh[i] = 0u;
    __syncthreads();
    const unsigned int pref = g_prefix;
    for (int i = blockIdx.x*blockDim.x + threadIdx.x; i < NSCORE;
         i += gridDim.x*blockDim.x) {
        unsigned int key = __float_as_uint(g_score[i]);
        if ((key & prefMask) == pref)
            atomicAdd(&sh[(key >> shift) & (nb-1)], 1u);
    }
    __syncthreads();
    for (int i = threadIdx.x; i < nb; i += blockDim.x)
        if (sh[i]) atomicAdd(&g_hist[i], sh[i]);
}

__global__ void scan_kernel(int shift, int bits, int last) {
    unsigned int kRem = g_kRem;
    const int nb = 1 << bits;
    for (int b = nb - 1; b >= 0; b--) {
        unsigned int c = g_hist[b];
        if (c >= kRem) { g_prefix |= ((unsigned int)b << shift); break; }
        kRem -= c;
    }
    g_kRem = kRem;
    if (last) { g_thresh = g_prefix; g_needEq = kRem; }
}

__global__ void compact_kernel() {
    const unsigned int T = g_thresh;
    for (int i = blockIdx.x*blockDim.x + threadIdx.x; i < NSCORE;
         i += gridDim.x*blockDim.x) {
        unsigned int key = __float_as_uint(g_score[i]);
        if (key > T) {
            unsigned int p = atomicAdd(&g_cntA, 1u);
            if (p < 512u)
                g_listA[p] = ((unsigned long long)key << 32) |
                             (unsigned int)(~(unsigned int)i);
        } else if (key == T) {
            unsigned int p = atomicAdd(&g_cntB, 1u);
            if (p < 4096u) g_listB[p] = (unsigned int)i;
        }
    }
}

// ================= final sort + decode =================
__global__ void final_kernel(float* __restrict__ out) {
    __shared__ unsigned long long comp[512];
    __shared__ unsigned int tie[4096];

    const int t = threadIdx.x;   // 512
    const unsigned int cntA = min(g_cntA, 512u);
    const unsigned int need = g_needEq;
    const unsigned int cntB = min(g_cntB, 4096u);
    const unsigned int T = g_thresh;

    // sort tie indices ascending (jax tie-break: lowest index first)
    for (int i = t; i < 4096; i += 512)
        tie[i] = (i < (int)cntB) ? g_listB[i] : 0xFFFFFFFFu;
    __syncthreads();
    for (int k = 2; k <= 4096; k <<= 1) {
        for (int j = k >> 1; j > 0; j >>= 1) {
            for (int i = t; i < 4096; i += 512) {
                int ixj = i ^ j;
                if (ixj > i) {
                    unsigned int a = tie[i], b = tie[ixj];
                    if ((i & k) == 0) { if (a > b) { tie[i] = b; tie[ixj] = a; } }
                    else             { if (a < b) { tie[i] = b; tie[ixj] = a; } }
                }
            }
            __syncthreads();
        }
    }

    // build composite list: strictly-greater + needed ties
    unsigned long long myc = 0ull;
    if (t < (int)cntA) {
        myc = g_listA[t];
    } else if (t < (int)(cntA + need)) {
        unsigned int r = t - cntA;
        if (r < cntB)
            myc = ((unsigned long long)T << 32) | (unsigned int)(~tie[r]);
    }
    comp[t] = myc;
    __syncthreads();

    // ascending bitonic sort on (key<<32)|~idx  (largest = best rank)
    for (int k = 2; k <= 512; k <<= 1) {
        for (int j = k >> 1; j > 0; j >>= 1) {
            int ixj = t ^ j;
            if (ixj > t) {
                unsigned long long a = comp[t], b = comp[ixj];
                if ((t & k) == 0) { if (a > b) { comp[t] = b; comp[ixj] = a; } }
                else              { if (a < b) { comp[t] = b; comp[ixj] = a; } }
            }
            __syncthreads();
        }
    }

    if (t < KTOP) {
        unsigned long long c = comp[511 - t];      // rank t (descending)
        unsigned int key = (unsigned int)(c >> 32);
        unsigned int idx = ~((unsigned int)(c & 0xFFFFFFFFull));
        float score = __uint_as_float(key);
        int cls = (int)(idx / HW);
        int sp  = (int)(idx % HW);
        float xs = (float)(sp % Ww);
        float ys = (float)(sp / Ww);

        float cx = g_reg[0*HW + sp], cy = g_reg[1*HW + sp];
        float cz = g_reg[2*HW + sp];
        float d0 = expf(g_reg[3*HW + sp]);
        float d1 = expf(g_reg[4*HW + sp]);
        float d2 = expf(g_reg[5*HW + sp]);
        float rc = g_reg[6*HW + sp], rs = g_reg[7*HW + sp];
        float iou = g_reg[8*HW + sp];

        float xg = ((xs + cx) * 4.0f) * 0.1f + (-75.2f);
        float yg = ((ys + cy) * 4.0f) * 0.1f + (-75.2f);
        float heading = atan2f(rs, rc);

        iou = fminf(fmaxf((iou + 1.0f) * 0.5f, 0.0f), 1.0f);
        const float RECT[3] = {0.68f, 0.71f, 0.65f};
        float r = RECT[cls];
        float sc = powf(score, 1.0f - r) * powf(iou, r);
        sc = (sc > 0.1f) ? sc : 0.0f;

        out[t*7 + 0] = xg;
        out[t*7 + 1] = yg;
        out[t*7 + 2] = cz;
        out[t*7 + 3] = d0;
        out[t*7 + 4] = d1;
        out[t*7 + 5] = d2;
        out[t*7 + 6] = heading;
        out[KTOP*7 + t]        = sc;
        out[KTOP*7 + KTOP + t] = (float)cls;
    }
}

// ================= launch =================
extern "C" void kernel_launch(void* const* d_in, const int* in_sizes, int n_in,
                              void* d_out, int out_size)
{
    const float* x    = (const float*)d_in[0];
    const float* Wsh  = (const float*)d_in[1];
    const float* bnsh = (const float*)d_in[2];
    const float* W1s  = (const float*)d_in[3];
    const float* bn1s = (const float*)d_in[4];
    const float* W2s  = (const float*)d_in[5];
    const float* b2s  = (const float*)d_in[6];
    float* out = (float*)d_out;

    static int smem_set = 0;
    if (!smem_set) {
        cudaFuncSetAttribute(winograd_kernel,
                             cudaFuncAttributeMaxDynamicSharedMemorySize, 131072);
        smem_set = 1;
    }

    // weight transforms (tiny)
    wtrans_kernel<<<dim3(64,1), 256>>>(Wsh, bnsh, CIN, 0);
    wtrans_kernel<<<dim3(16,NB), 256>>>(W1s, bn1s, CSH, 1);

    // Winograd convs: shared (256->64) then 6 branches (64->64)
    winograd_kernel<<<dim3(6,188,1), 512, 131072>>>(x, 0, CIN);
    winograd_kernel<<<dim3(6,188,NB), 512, 131072>>>(nullptr, 1, CSH);

    // final 64->3 convs
    conv2_kernel<<<dim3(3,94,NB), 128>>>(W2s, b2s);

    init_kernel<<<1,1>>>();
    // pass 0: bits [31:21]
    zero_hist_kernel<<<2,1024>>>();
    hist_kernel<<<512,256>>>(0x00000000u, 21, 11);
    scan_kernel<<<1,1>>>(21, 11, 0);
    // pass 1: bits [20:10]
    zero_hist_kernel<<<2,1024>>>();
    hist_kernel<<<512,256>>>(0xFFE00000u, 10, 11);
    scan_kernel<<<1,1>>>(10, 11, 0);
    // pass 2: bits [9:0]
    zero_hist_kernel<<<2,1024>>>();
    hist_kernel<<<512,256>>>(0xFFFFFC00u, 0, 10);
    scan_kernel<<<1,1>>>(0, 10, 1);

    compact_kernel<<<512,256>>>();
    final_kernel<<<1,512>>>(out);
}

// round 13
// speedup vs baseline: 2.2781x; 1.6343x over previous
#include <cuda_runtime.h>
#include <math.h>

// ---------------- static config ----------------
#define Hh   376
#define Ww   376
#define HW   (376*376)          // 141376
#define CIN  256
#define CSH  64
#define NB   6
#define KTOP 500
#define NSCORE (3*HW)           // 424128
#define BN_EPS 1e-5f

// ---------------- scratch (device globals; no runtime alloc) ----------------
__device__ float g_shared[CSH*HW];        // shared conv output (post BN+ReLU)
__device__ float g_h[NB*CSH*HW];          // branch hidden activations
__device__ float g_score[3*HW];           // sigmoid(hm)
__device__ float g_reg[9*HW];             // center(2), cz(1), dim(3), rot(2), iou(1)

// Winograd transformed weights (BN scale folded) + bias
// layout: U[(ci*16 + k)*64 + co]  -> per-8ci chunk is one contiguous 32KB slab
__device__ float g_U_sh[16*CIN*CSH];
__device__ float g_U_br[NB*16*CSH*CSH];
__device__ float g_bias_sh[CSH];
__device__ float g_bias_br[NB*CSH];

__device__ unsigned int g_hist[2048];
__device__ unsigned int g_prefix;
__device__ unsigned int g_kRem;
__device__ unsigned int g_cntA;
__device__ unsigned int g_cntB;
__device__ unsigned int g_thresh;
__device__ unsigned int g_needEq;
__device__ unsigned long long g_listA[512];
__device__ unsigned int g_listB[4096];

// slot map: branch -> global reg slot per out-channel (-1 = unused)
__device__ __constant__ int c_slot[NB][3] = {
    {-1,-1,-1},   // hm handled separately (g_score)
    { 0, 1,-1},   // center
    { 2,-1,-1},   // center_z
    { 3, 4, 5},   // dim
    { 6, 7,-1},   // rot
    { 8,-1,-1}    // iou
};

// ================= weight transform: U = (G g G^T) * bn_scale ==============
// layout out: U[(ci*16 + k)*64 + co]
__global__ void wtrans_kernel(const float* __restrict__ W,
                              const float* __restrict__ bn,
                              int cin, int mode)
{
    float* U;
    float* bias;
    if (mode == 0) {
        U = g_U_sh; bias = g_bias_sh;
    } else {
        int br = blockIdx.y;
        W  += (size_t)br * CSH * CSH * 9;
        bn += br * 4 * CSH;
        U = g_U_br + (size_t)br * 16 * CSH * CSH;
        bias = g_bias_br + br * CSH;
    }
    int idx = blockIdx.x * blockDim.x + threadIdx.x;
    if (idx >= 64 * cin) return;
    int co = idx / cin, ci = idx % cin;

    float scale = bn[0*CSH+co] * rsqrtf(bn[3*CSH+co] + BN_EPS);
    float g[9];
    #pragma unroll
    for (int k = 0; k < 9; k++) g[k] = W[(size_t)(co*cin + ci)*9 + k] * scale;

    float t[4][3];
    #pragma unroll
    for (int c = 0; c < 3; c++) {
        t[0][c] = g[0*3+c];
        t[1][c] = 0.5f*(g[0*3+c] + g[1*3+c] + g[2*3+c]);
        t[2][c] = 0.5f*(g[0*3+c] - g[1*3+c] + g[2*3+c]);
        t[3][c] = g[2*3+c];
    }
    #pragma unroll
    for (int r = 0; r < 4; r++) {
        float u0 = t[r][0];
        float u1 = 0.5f*(t[r][0] + t[r][1] + t[r][2]);
        float u2 = 0.5f*(t[r][0] - t[r][1] + t[r][2]);
        float u3 = t[r][2];
        U[(size_t)(ci*16 + r*4+0)*64 + co] = u0;
        U[(size_t)(ci*16 + r*4+1)*64 + co] = u1;
        U[(size_t)(ci*16 + r*4+2)*64 + co] = u2;
        U[(size_t)(ci*16 + r*4+3)*64 + co] = u3;
    }
    if (ci == 0) bias[co] = bn[1*CSH+co] - bn[2*CSH+co]*scale;
}

// ================= fused Winograd F(2x2,3x3), double-buffered pipeline =====
// block: 512 threads = 16 warps; warp k owns transform point k in the GEMM.
// tile block: 32 tiles x-wise (64 out px) x 1 tile row (2 out rows).
// thread GEMM tile: 8 cout x 8 tiles; cin chunks of 8, 1 sync per chunk.
// Roles: tid<256 produce V (LDG raw patch -> reg transform -> STS);
//        tid>=256 prefetch U slab (coalesced float4).
// smem: Vbuf0[4096] Vbuf1[4096] Ubuf0[8192] Ubuf1[8192]; M overlays [0,32768)

#define U_CHUNK_F4 2048   // one 8-ci chunk of U = 8*16*64 floats = 2048 float4

__global__ void __launch_bounds__(512, 1)
winograd_kernel(const float* __restrict__ xin, int mode, int cin)
{
    extern __shared__ float sm[];

    const float* in;
    const float* U;
    const float* bias;
    float* out;
    if (mode == 0) {
        in = xin; U = g_U_sh; bias = g_bias_sh; out = g_shared;
    } else {
        int br = blockIdx.z;
        in = g_shared;
        U = g_U_br + (size_t)br * 16 * CSH * CSH;
        bias = g_bias_br + br * CSH;
        out = g_h + (size_t)br * CSH * HW;
    }

    const int tid = threadIdx.x;
    const int k = tid >> 5;            // GEMM transform point (warp)
    const int lane = tid & 31;
    const int co0 = (lane >> 2) * 8;
    const int t0 = (lane & 3) * 8;

    const int T0 = blockIdx.x * 32;    // first tile index (x)
    const int x0px = T0*2 - 1;
    const int y0px = (int)blockIdx.y*2 - 1;

    const bool isV = (tid < 256);
    // V-producer indices
    const int vci = tid >> 5;          // 0..7 (valid when isV)
    const int vt  = tid & 31;
    const int xb  = x0px + 2*vt;
    // U-prefetcher index
    const int f = tid & 255;

    const int nCh = cin >> 3;

    float acc[8][8];
    #pragma unroll
    for (int a = 0; a < 8; a++)
        #pragma unroll
        for (int b = 0; b < 8; b++) acc[a][b] = 0.f;

    float st[32];   // staging regs: V role uses 16, U role uses 32

#define PREFETCH(c)                                                          \
    do {                                                                     \
        if (isV) {                                                           \
            const float* base = in + (size_t)((c)*8 + vci)*HW;               \
            _Pragma("unroll")                                                \
            for (int r = 0; r < 4; r++) {                                    \
                int yy = y0px + r;                                           \
                bool yv = (unsigned)yy < (unsigned)Hh;                       \
                const float* rp = base + yy*Ww + xb;                         \
                _Pragma("unroll")                                            \
                for (int cc = 0; cc < 4; cc++) {                             \
                    bool ok = yv && ((unsigned)(xb+cc) < (unsigned)Ww);      \
                    st[r*4+cc] = ok ? rp[cc] : 0.f;                          \
                }                                                            \
            }                                                                \
        } else {                                                             \
            const float4* src = (const float4*)U + (size_t)(c)*U_CHUNK_F4;   \
            _Pragma("unroll")                                                \
            for (int j = 0; j < 8; j++)                                      \
                ((float4*)st)[j] = src[j*256 + f];                           \
        }                                                                    \
    } while (0)

#define STOBUF(buf)                                                          \
    do {                                                                     \
        if (isV) {                                                           \
            float z[4][4];                                                   \
            _Pragma("unroll")                                                \
            for (int c2 = 0; c2 < 4; c2++) {                                 \
                z[0][c2] = st[0*4+c2] - st[2*4+c2];                          \
                z[1][c2] = st[1*4+c2] + st[2*4+c2];                          \
                z[2][c2] = st[2*4+c2] - st[1*4+c2];                          \
                z[3][c2] = st[1*4+c2] - st[3*4+c2];                          \
            }                                                                \
            float* vb = &sm[(buf)*4096 + vci*512];                           \
            _Pragma("unroll")                                                \
            for (int r = 0; r < 4; r++) {                                    \
                vb[(r*4+0)*32 + vt] = z[r][0] - z[r][2];                     \
                vb[(r*4+1)*32 + vt] = z[r][1] + z[r][2];                     \
                vb[(r*4+2)*32 + vt] = z[r][2] - z[r][1];                     \
                vb[(r*4+3)*32 + vt] = z[r][1] - z[r][3];                     \
            }                                                                \
        } else {                                                             \
            float4* db = (float4*)&sm[8192 + (buf)*8192];                    \
            _Pragma("unroll")                                                \
            for (int j = 0; j < 8; j++)                                      \
                db[j*256 + f] = ((float4*)st)[j];                            \
        }                                                                    \
    } while (0)

    // prologue: chunk 0 -> buffer 0
    PREFETCH(0);
    STOBUF(0);
    __syncthreads();

    for (int c = 0; c < nCh; c++) {
        const int buf = c & 1;
        if (c+1 < nCh) PREFETCH(c+1);

        // GEMM on current buffer
        {
            const float* Ub = &sm[8192 + buf*8192 + k*64 + co0];
            const float* Vb = &sm[buf*4096 + k*32 + t0];
            #pragma unroll
            for (int ci = 0; ci < 8; ci++) {
                float4 ua = *(const float4*)(Ub + ci*1024);
                float4 ub = *(const float4*)(Ub + ci*1024 + 4);
                float4 va = *(const float4*)(Vb + ci*512);
                float4 vb2 = *(const float4*)(Vb + ci*512 + 4);
                float u[8] = {ua.x,ua.y,ua.z,ua.w, ub.x,ub.y,ub.z,ub.w};
                float v[8] = {va.x,va.y,va.z,va.w, vb2.x,vb2.y,vb2.z,vb2.w};
                #pragma unroll
                for (int a = 0; a < 8; a++)
                    #pragma unroll
                    for (int b = 0; b < 8; b++)
                        acc[a][b] = fmaf(u[a], v[b], acc[a][b]);
            }
        }

        if (c+1 < nCh) STOBUF((c+1) & 1);
        __syncthreads();
    }

    // ---- cross-warp output transform via swizzled smem M buffer ----
    #pragma unroll
    for (int a = 0; a < 8; a++) {
        int co = co0 + a;
        int sw = t0 ^ ((co & 7) << 2);
        float4 lo = make_float4(acc[a][0], acc[a][1], acc[a][2], acc[a][3]);
        float4 hi = make_float4(acc[a][4], acc[a][5], acc[a][6], acc[a][7]);
        *(float4*)&sm[k*2048 + co*32 + sw]       = lo;
        *(float4*)&sm[k*2048 + co*32 + (sw ^ 4)] = hi;
    }
    __syncthreads();

    const int gy = blockIdx.y * 2;
    for (int task = tid; task < 2048; task += 512) {
        int co = task >> 5, t = task & 31;
        int colsw = t ^ ((co & 7) << 2);
        float m[16];
        #pragma unroll
        for (int kk = 0; kk < 16; kk++) m[kk] = sm[kk*2048 + co*32 + colsw];
        float p0[4], p1[4];
        #pragma unroll
        for (int c = 0; c < 4; c++) {
            p0[c] = m[c] + m[4+c] + m[8+c];
            p1[c] = m[4+c] - m[8+c] - m[12+c];
        }
        float bi = bias[co];
        float y00 = fmaxf(p0[0]+p0[1]+p0[2] + bi, 0.f);
        float y01 = fmaxf(p0[1]-p0[2]-p0[3] + bi, 0.f);
        float y10 = fmaxf(p1[0]+p1[1]+p1[2] + bi, 0.f);
        float y11 = fmaxf(p1[1]-p1[2]-p1[3] + bi, 0.f);
        int gx = (T0 + t) * 2;
        if (gx < Ww) {
            float* o = out + (size_t)co*HW + gy*Ww + gx;
            *(float2*)o         = make_float2(y00, y01);
            *(float2*)(o + Ww)  = make_float2(y10, y11);
        }
    }
#undef PREFETCH
#undef STOBUF
}

// ================= branch conv2: 64 -> 3, 3x3 + bias (x6) =================
// block: 128 threads, tile = 4 rows x 128 px, thread = 1 px x 3 oc x 4 rows
#define C2W 128
__global__ void conv2_kernel(const float* __restrict__ W2s,
                             const float* __restrict__ b2s)
{
    __shared__ float s_in[6][C2W+2];
    __shared__ float s_w[27];

    const int br = blockIdx.z;
    const float* __restrict__ in = g_h + (size_t)br*CSH*HW;
    const float* __restrict__ Wb = W2s + (size_t)br*3*CSH*9;

    const int y0 = blockIdx.y * 4;
    const int x0 = blockIdx.x * C2W;
    const int t  = threadIdx.x;

    float acc[4][3];
    #pragma unroll
    for (int j = 0; j < 4; j++)
        #pragma unroll
        for (int o = 0; o < 3; o++) acc[j][o] = 0.f;

    for (int c = 0; c < CSH; c++) {
        __syncthreads();
        for (int i = t; i < 6*(C2W+2); i += C2W) {
            int r = i / (C2W+2), cc = i % (C2W+2);
            int iy = y0 - 1 + r, ix = x0 - 1 + cc;
            float v = 0.f;
            if ((unsigned)iy < (unsigned)Hh && (unsigned)ix < (unsigned)Ww)
                v = in[c*HW + iy*Ww + ix];
            s_in[r][cc] = v;
        }
        if (t < 27) s_w[t] = Wb[((t/9)*CSH + c)*9 + (t%9)];
        __syncthreads();

        float w[3][9];
        #pragma unroll
        for (int o = 0; o < 3; o++)
            #pragma unroll
            for (int kk = 0; kk < 9; kk++) w[o][kk] = s_w[o*9+kk];

        #pragma unroll
        for (int r = 0; r < 6; r++) {
            float a0 = s_in[r][t], a1 = s_in[r][t+1], a2 = s_in[r][t+2];
            #pragma unroll
            for (int j = 0; j < 4; j++) {
                int ky = r - j;
                if (ky >= 0 && ky < 3) {
                    #pragma unroll
                    for (int o = 0; o < 3; o++)
                        acc[j][o] += w[o][ky*3]*a0 + w[o][ky*3+1]*a1 + w[o][ky*3+2]*a2;
                }
            }
        }
    }

    int gx = x0 + t;
    if (gx < Ww) {
        #pragma unroll
        for (int j = 0; j < 4; j++) {
            int p = (y0+j)*Ww + gx;
            #pragma unroll
            for (int o = 0; o < 3; o++) {
                float v = acc[j][o] + b2s[br*3 + o];
                if (br == 0) {
                    g_score[o*HW + p] = 1.f / (1.f + expf(-v));
                } else {
                    int slot = c_slot[br][o];
                    if (slot >= 0) g_reg[slot*HW + p] = v;
                }
            }
        }
    }
}

// ================= exact top-K: 3-pass radix select =================
__global__ void init_kernel() {
    g_prefix = 0u; g_kRem = KTOP; g_cntA = 0u; g_cntB = 0u;
}

__global__ void zero_hist_kernel() {
    int i = blockIdx.x * blockDim.x + threadIdx.x;
    if (i < 2048) g_hist[i] = 0u;
}

__global__ void hist_kernel(unsigned int prefMask, int shift, int bits) {
    __shared__ unsigned int sh[2048];
    const int nb = 1 << bits;
    for (int i = threadIdx.x; i < nb; i += blockDim.x) sh[i] = 0u;
    __syncthreads();
    const unsigned int pref = g_prefix;
    for (int i = blockIdx.x*blockDim.x + threadIdx.x; i < NSCORE;
         i += gridDim.x*blockDim.x) {
        unsigned int key = __float_as_uint(g_score[i]);
        if ((key & prefMask) == pref)
            atomicAdd(&sh[(key >> shift) & (nb-1)], 1u);
    }
    __syncthreads();
    for (int i = threadIdx.x; i < nb; i += blockDim.x)
        if (sh[i]) atomicAdd(&g_hist[i], sh[i]);
}

__global__ void scan_kernel(int shift, int bits, int last) {
    unsigned int kRem = g_kRem;
    const int nb = 1 << bits;
    for (int b = nb - 1; b >= 0; b--) {
        unsigned int c = g_hist[b];
        if (c >= kRem) { g_prefix |= ((unsigned int)b << shift); break; }
        kRem -= c;
    }
    g_kRem = kRem;
    if (last) { g_thresh = g_prefix; g_needEq = kRem; }
}

__global__ void compact_kernel() {
    const unsigned int T = g_thresh;
    for (int i = blockIdx.x*blockDim.x + threadIdx.x; i < NSCORE;
         i += gridDim.x*blockDim.x) {
        unsigned int key = __float_as_uint(g_score[i]);
        if (key > T) {
            unsigned int p = atomicAdd(&g_cntA, 1u);
            if (p < 512u)
                g_listA[p] = ((unsigned long long)key << 32) |
                             (unsigned int)(~(unsigned int)i);
        } else if (key == T) {
            unsigned int p = atomicAdd(&g_cntB, 1u);
            if (p < 4096u) g_listB[p] = (unsigned int)i;
        }
    }
}

// ================= final sort + decode =================
__global__ void final_kernel(float* __restrict__ out) {
    __shared__ unsigned long long comp[512];
    __shared__ unsigned int tie[4096];

    const int t = threadIdx.x;   // 512
    const unsigned int cntA = min(g_cntA, 512u);
    const unsigned int need = g_needEq;
    const unsigned int cntB = min(g_cntB, 4096u);
    const unsigned int T = g_thresh;

    // sort tie indices ascending (jax tie-break: lowest index first)
    for (int i = t; i < 4096; i += 512)
        tie[i] = (i < (int)cntB) ? g_listB[i] : 0xFFFFFFFFu;
    __syncthreads();
    for (int k = 2; k <= 4096; k <<= 1) {
        for (int j = k >> 1; j > 0; j >>= 1) {
            for (int i = t; i < 4096; i += 512) {
                int ixj = i ^ j;
                if (ixj > i) {
                    unsigned int a = tie[i], b = tie[ixj];
                    if ((i & k) == 0) { if (a > b) { tie[i] = b; tie[ixj] = a; } }
                    else             { if (a < b) { tie[i] = b; tie[ixj] = a; } }
                }
            }
            __syncthreads();
        }
    }

    // build composite list: strictly-greater + needed ties
    unsigned long long myc = 0ull;
    if (t < (int)cntA) {
        myc = g_listA[t];
    } else if (t < (int)(cntA + need)) {
        unsigned int r = t - cntA;
        if (r < cntB)
            myc = ((unsigned long long)T << 32) | (unsigned int)(~tie[r]);
    }
    comp[t] = myc;
    __syncthreads();

    // ascending bitonic sort on (key<<32)|~idx  (largest = best rank)
    for (int k = 2; k <= 512; k <<= 1) {
        for (int j = k >> 1; j > 0; j >>= 1) {
            int ixj = t ^ j;
            if (ixj > t) {
                unsigned long long a = comp[t], b = comp[ixj];
                if ((t & k) == 0) { if (a > b) { comp[t] = b; comp[ixj] = a; } }
                else              { if (a < b) { comp[t] = b; comp[ixj] = a; } }
            }
            __syncthreads();
        }
    }

    if (t < KTOP) {
        unsigned long long c = comp[511 - t];      // rank t (descending)
        unsigned int key = (unsigned int)(c >> 32);
        unsigned int idx = ~((unsigned int)(c & 0xFFFFFFFFull));
        float score = __uint_as_float(key);
        int cls = (int)(idx / HW);
        int sp  = (int)(idx % HW);
        float xs = (float)(sp % Ww);
        float ys = (float)(sp / Ww);

        float cx = g_reg[0*HW + sp], cy = g_reg[1*HW + sp];
        float cz = g_reg[2*HW + sp];
        float d0 = expf(g_reg[3*HW + sp]);
        float d1 = expf(g_reg[4*HW + sp]);
        float d2 = expf(g_reg[5*HW + sp]);
        float rc = g_reg[6*HW + sp], rs = g_reg[7*HW + sp];
        float iou = g_reg[8*HW + sp];

        float xg = ((xs + cx) * 4.0f) * 0.1f + (-75.2f);
        float yg = ((ys + cy) * 4.0f) * 0.1f + (-75.2f);
        float heading = atan2f(rs, rc);

        iou = fminf(fmaxf((iou + 1.0f) * 0.5f, 0.0f), 1.0f);
        const float RECT[3] = {0.68f, 0.71f, 0.65f};
        float r = RECT[cls];
        float sc = powf(score, 1.0f - r) * powf(iou, r);
        sc = (sc > 0.1f) ? sc : 0.0f;

        out[t*7 + 0] = xg;
        out[t*7 + 1] = yg;
        out[t*7 + 2] = cz;
        out[t*7 + 3] = d0;
        out[t*7 + 4] = d1;
        out[t*7 + 5] = d2;
        out[t*7 + 6] = heading;
        out[KTOP*7 + t]        = sc;
        out[KTOP*7 + KTOP + t] = (float)cls;
    }
}

// ================= launch =================
extern "C" void kernel_launch(void* const* d_in, const int* in_sizes, int n_in,
                              void* d_out, int out_size)
{
    const float* x    = (const float*)d_in[0];
    const float* Wsh  = (const float*)d_in[1];
    const float* bnsh = (const float*)d_in[2];
    const float* W1s  = (const float*)d_in[3];
    const float* bn1s = (const float*)d_in[4];
    const float* W2s  = (const float*)d_in[5];
    const float* b2s  = (const float*)d_in[6];
    float* out = (float*)d_out;

    static int smem_set = 0;
    if (!smem_set) {
        cudaFuncSetAttribute(winograd_kernel,
                             cudaFuncAttributeMaxDynamicSharedMemorySize, 131072);
        smem_set = 1;
    }

    // weight transforms (tiny)
    wtrans_kernel<<<dim3(64,1), 256>>>(Wsh, bnsh, CIN, 0);
    wtrans_kernel<<<dim3(16,NB), 256>>>(W1s, bn1s, CSH, 1);

    // Winograd convs: shared (256->64) then 6 branches (64->64)
    winograd_kernel<<<dim3(6,188,1), 512, 131072>>>(x, 0, CIN);
    winograd_kernel<<<dim3(6,188,NB), 512, 131072>>>(nullptr, 1, CSH);

    // final 64->3 convs
    conv2_kernel<<<dim3(3,94,NB), 128>>>(W2s, b2s);

    init_kernel<<<1,1>>>();
    // pass 0: bits [31:21]
    zero_hist_kernel<<<2,1024>>>();
    hist_kernel<<<512,256>>>(0x00000000u, 21, 11);
    scan_kernel<<<1,1>>>(21, 11, 0);
    // pass 1: bits [20:10]
    zero_hist_kernel<<<2,1024>>>();
    hist_kernel<<<512,256>>>(0xFFE00000u, 10, 11);
    scan_kernel<<<1,1>>>(10, 11, 0);
    // pass 2: bits [9:0]
    zero_hist_kernel<<<2,1024>>>();
    hist_kernel<<<512,256>>>(0xFFFFFC00u, 0, 10);
    scan_kernel<<<1,1>>>(0, 10, 1);

    compact_kernel<<<512,256>>>();
    final_kernel<<<1,512>>>(out);
}